// round 5
// baseline (speedup 1.0000x reference)
#include <cuda_runtime.h>

typedef unsigned long long u64;

#define NITER 31
#define BLOCK 256

__device__ double   g_sum   = 0.0;
__device__ unsigned g_count = 0;

__device__ __forceinline__ u64 pk2(float a, float b) {
    u64 r; asm("mov.b64 %0, {%1, %2};" : "=l"(r) : "f"(a), "f"(b)); return r;
}
__device__ __forceinline__ void up2(u64 v, float &a, float &b) {
    asm("mov.b64 {%0, %1}, %2;" : "=f"(a), "=f"(b) : "l"(v));
}
__device__ __forceinline__ u64 ffma2(u64 a, u64 b, u64 c) {
    u64 d; asm("fma.rn.f32x2 %0, %1, %2, %3;" : "=l"(d) : "l"(a), "l"(b), "l"(c)); return d;
}
__device__ __forceinline__ u64 fmul2(u64 a, u64 b) {
    u64 d; asm("mul.rn.f32x2 %0, %1, %2;" : "=l"(d) : "l"(a), "l"(b)); return d;
}
__device__ __forceinline__ u64 fsub2(u64 a, u64 b) {
    u64 d; asm("sub.rn.f32x2 %0, %1, %2;" : "=l"(d) : "l"(a), "l"(b)); return d;
}
__device__ __forceinline__ float frcp_(float x) {
    float r; asm("rcp.approx.f32 %0, %1;" : "=f"(r) : "f"(x)); return r;
}

__global__ void __launch_bounds__(BLOCK)
lm_kernel(const float* __restrict__ P, const float* __restrict__ V,
          const float* __restrict__ R, const float* __restrict__ T,
          const float* __restrict__ Cs, const float* __restrict__ loss_in,
          float* __restrict__ out, int n, double invN)
{
    const int tid0   = blockIdx.x * BLOCK + threadIdx.x;
    const int stride = gridDim.x * BLOCK;
    const int nchunks = n >> 2;            // full chunks of 4 rays

    const float r00 = __ldg(R + 0), r01 = __ldg(R + 1), r02 = __ldg(R + 2);
    const float r10 = __ldg(R + 3), r11 = __ldg(R + 4), r12 = __ldg(R + 5);
    const float r20 = __ldg(R + 6), r21 = __ldg(R + 7), r22 = __ldg(R + 8);
    const float tx = __ldg(T + 0), ty = __ldg(T + 1), tz = __ldg(T + 2);
    const float c   = __ldg(Cs);
    const float mc  = -c;
    const float m2c = -2.0f * c;

    const u64 TWO2 = 0x4000000040000000ULL;  // (2, 2)
    const u64 ONE2 = 0x3F8000003F800000ULL;  // (1, 1)

    const float4* P4 = (const float4*)P;
    const float4* V4 = (const float4*)V;

    double dsum = 0.0;

    int  cid  = tid0;
    bool have = cid < nchunks;
    float4 a0, a1, a2, b0, b1, b2;
    if (have) {
        a0 = P4[3*cid + 0]; a1 = P4[3*cid + 1]; a2 = P4[3*cid + 2];
        b0 = V4[3*cid + 0]; b1 = V4[3*cid + 1]; b2 = V4[3*cid + 2];
    }

    while (have) {
        // ---- consume current chunk: transform -> per-ray (D, s0, 1/4A) ----
        float px[4], py[4], pz[4], wx[4], wy[4], wz[4];
        px[0]=a0.x; py[0]=a0.y; pz[0]=a0.z;
        px[1]=a0.w; py[1]=a1.x; pz[1]=a1.y;
        px[2]=a1.z; py[2]=a1.w; pz[2]=a2.x;
        px[3]=a2.y; py[3]=a2.z; pz[3]=a2.w;
        wx[0]=b0.x; wy[0]=b0.y; wz[0]=b0.z;
        wx[1]=b0.w; wy[1]=b1.x; wz[1]=b1.y;
        wx[2]=b1.z; wy[2]=b1.w; wz[2]=b2.x;
        wx[3]=b2.y; wy[3]=b2.z; wz[3]=b2.w;

        float Dk[4], Sk[4], I4[4];
        #pragma unroll
        for (int k = 0; k < 4; ++k) {
            float qx = px[k] - tx, qy = py[k] - ty, qz = pz[k] - tz;
            float plx = qx*r00 + qy*r10 + qz*r20;
            float ply = qx*r01 + qy*r11 + qz*r21;
            float plz = qx*r02 + qy*r12 + qz*r22;
            float vlx = wx[k]*r00 + wy[k]*r10 + wz[k]*r20;
            float vly = wx[k]*r01 + wy[k]*r11 + wz[k]*r21;
            float vlz = wx[k]*r02 + wy[k]*r12 + wz[k]*r22;
            float A = mc * (vly*vly + vlz*vlz);
            float B = fmaf(m2c, ply*vly + plz*vlz, vlx);
            float C = fmaf(mc,  ply*ply + plz*plz, plx);
            if (A == 0.0f) { A = 1.0f; B = 1.0f; C = 0.0f; }  // degenerate guard
            float AC = A * C;
            Dk[k] = fmaf(AC, -4.0f, B * B);   // D = B^2 - 4AC
            Sk[k] = B;                        // s0 = B
            I4[k] = frcp_(4.0f * A);          // 1/(4A) for the epilogue
        }

        // ---- prefetch next chunk (overlaps with the 31-iteration compute) ----
        int  nid  = cid + stride;
        bool more = nid < nchunks;
        float4 na0, na1, na2, nb0, nb1, nb2;
        if (more) {
            na0 = P4[3*nid + 0]; na1 = P4[3*nid + 1]; na2 = P4[3*nid + 2];
            nb0 = V4[3*nid + 0]; nb1 = V4[3*nid + 1]; nb2 = V4[3*nid + 2];
        }

        // ---- 31 LM iterations in s-space: s' = s - s(s^2-D)/(2s^2+1) ----
        const u64 D0 = pk2(Dk[0], Dk[1]), D1 = pk2(Dk[2], Dk[3]);
        const u64 I40 = pk2(I4[0], I4[1]), I41 = pk2(I4[2], I4[3]);
        u64 s0 = pk2(Sk[0], Sk[1]),        s1 = pk2(Sk[2], Sk[3]);

        #pragma unroll
        for (int it = 0; it < NITER; ++it) {
            u64 q0 = fmul2(s0, s0);
            u64 q1 = fmul2(s1, s1);
            u64 w0 = fsub2(D0, q0);          // D - s^2
            u64 w1 = fsub2(D1, q1);
            u64 d0 = ffma2(q0, TWO2, ONE2);  // 2 s^2 + 1  (>= 1)
            u64 d1 = ffma2(q1, TWO2, ONE2);
            u64 n0 = fmul2(s0, w0);
            u64 n1 = fmul2(s1, w1);
            u64 m  = fmul2(d0, d1);          // shared reciprocal trick
            float ma, mb; up2(m, ma, mb);
            u64 rp = pk2(frcp_(ma), frcp_(mb));
            u64 r0 = fmul2(rp, d1);          // 1/d0
            u64 r1 = fmul2(rp, d0);          // 1/d1
            s0 = ffma2(n0, r0, s0);
            s1 = ffma2(n1, r1, s1);
        }

        // ---- F = (s^2 - D)/(4A); accumulate F^2 ----
        u64 q0 = fmul2(s0, s0);
        u64 q1 = fmul2(s1, s1);
        u64 w0 = fsub2(D0, q0);
        u64 w1 = fsub2(D1, q1);
        u64 F0 = fmul2(w0, I40);
        u64 F1 = fmul2(w1, I41);
        u64 ss = fmul2(F0, F0);
        ss = ffma2(F1, F1, ss);
        float sa, sb; up2(ss, sa, sb);
        dsum += (double)(sa + sb);

        // ---- rotate pipeline ----
        cid = nid; have = more;
        if (more) { a0=na0; a1=na1; a2=na2; b0=nb0; b1=nb1; b2=nb2; }
    }

    // remainder rays (n % 4), scalar path on one thread (dead for n = 2^22)
    if (tid0 == 0) {
        for (int i = (nchunks << 2); i < n; ++i) {
            float qx = P[3*i] - tx, qy = P[3*i+1] - ty, qz = P[3*i+2] - tz;
            float plx = qx*r00 + qy*r10 + qz*r20;
            float ply = qx*r01 + qy*r11 + qz*r21;
            float plz = qx*r02 + qy*r12 + qz*r22;
            float vlx = V[3*i]*r00 + V[3*i+1]*r10 + V[3*i+2]*r20;
            float vly = V[3*i]*r01 + V[3*i+1]*r11 + V[3*i+2]*r21;
            float vlz = V[3*i]*r02 + V[3*i+1]*r12 + V[3*i+2]*r22;
            float A = mc * (vly*vly + vlz*vlz);
            float B = fmaf(m2c, ply*vly + plz*vlz, vlx);
            float C = fmaf(mc,  ply*ply + plz*plz, plx);
            if (A == 0.0f) { A = 1.0f; B = 1.0f; C = 0.0f; }
            float D = fmaf(A*C, -4.0f, B*B);
            float s = B;
            for (int it = 0; it < NITER; ++it) {
                float q = s*s;
                float w = D - q;
                float d = fmaf(q, 2.0f, 1.0f);
                s = fmaf(s*w, frcp_(d), s);
            }
            float F = (s*s - D) * frcp_(4.0f*A);
            dsum += (double)(F*F);
        }
    }

    // ---- block tree reduction (double) ----
    #pragma unroll
    for (int o = 16; o > 0; o >>= 1)
        dsum += __shfl_xor_sync(0xffffffffu, dsum, o);
    __shared__ double wsum[BLOCK / 32];
    if ((threadIdx.x & 31) == 0) wsum[threadIdx.x >> 5] = dsum;
    __syncthreads();

    if (threadIdx.x == 0) {
        double bsum = 0.0;
        #pragma unroll
        for (int w = 0; w < BLOCK / 32; ++w) bsum += wsum[w];
        atomicAdd(&g_sum, bsum);
        __threadfence();
        unsigned old = atomicAdd(&g_count, 1u);
        if (old == gridDim.x - 1) {          // last block finalizes & resets
            __threadfence();
            double tot = g_sum;
            out[0] = (float)((double)loss_in[0] + tot * invN);
            g_sum = 0.0;
            __threadfence();
            g_count = 0;
        }
    }
}

extern "C" void kernel_launch(void* const* d_in, const int* in_sizes, int n_in,
                              void* d_out, int out_size)
{
    const float* P       = (const float*)d_in[0];
    const float* V       = (const float*)d_in[1];
    const float* R       = (const float*)d_in[2];
    const float* T       = (const float*)d_in[3];
    const float* c       = (const float*)d_in[4];
    const float* loss_in = (const float*)d_in[5];

    const int n = in_sizes[0] / 3;            // number of rays

    // one resident wave of persistent grid-stride blocks
    int nb = 0, sms = 0;
    cudaOccupancyMaxActiveBlocksPerMultiprocessor(&nb, lm_kernel, BLOCK, 0);
    cudaDeviceGetAttribute(&sms, cudaDevAttrMultiProcessorCount, 0);
    long long grid = (long long)(nb > 0 ? nb : 4) * (sms > 0 ? sms : 148);
    long long maxg = ((long long)(n >> 2) + BLOCK - 1) / BLOCK;
    if (maxg < 1) maxg = 1;
    if (grid > maxg) grid = maxg;

    lm_kernel<<<(int)grid, BLOCK>>>(P, V, R, T, c, loss_in,
                                    (float*)d_out, n, 1.0 / (double)n);
}

// round 6
// speedup vs baseline: 1.0818x; 1.0818x over previous
#include <cuda_runtime.h>

typedef unsigned long long u64;

#define NITER 31
#define BLOCK 256

__device__ double   g_sum   = 0.0;
__device__ unsigned g_count = 0;

__device__ __forceinline__ u64 pk2(float a, float b) {
    u64 r; asm("mov.b64 %0, {%1, %2};" : "=l"(r) : "f"(a), "f"(b)); return r;
}
__device__ __forceinline__ void up2(u64 v, float &a, float &b) {
    asm("mov.b64 {%0, %1}, %2;" : "=f"(a), "=f"(b) : "l"(v));
}
__device__ __forceinline__ u64 ffma2(u64 a, u64 b, u64 c) {
    u64 d; asm("fma.rn.f32x2 %0, %1, %2, %3;" : "=l"(d) : "l"(a), "l"(b), "l"(c)); return d;
}
__device__ __forceinline__ u64 fmul2(u64 a, u64 b) {
    u64 d; asm("mul.rn.f32x2 %0, %1, %2;" : "=l"(d) : "l"(a), "l"(b)); return d;
}
__device__ __forceinline__ u64 fsub2(u64 a, u64 b) {
    u64 d; asm("sub.rn.f32x2 %0, %1, %2;" : "=l"(d) : "l"(a), "l"(b)); return d;
}
__device__ __forceinline__ float frcp_(float x) {
    float r; asm("rcp.approx.f32 %0, %1;" : "=f"(r) : "f"(x)); return r;
}

// Per-ray quadratic setup using |V_local| = 1 and rotation invariance:
//   A = -c (1 - vlx^2)
//   B = vlx + 2c (plx*vlx - (P-T).V)
//   C = plx + c (plx^2 - |P-T|^2)
// Only column 0 of R is needed.
struct RayQ { float D, s, i4; };

__device__ __forceinline__ RayQ setup_ray(
    float px, float py, float pz, float wx, float wy, float wz,
    float r00, float r10, float r20, float tx, float ty, float tz,
    float c, float mc, float twoc)
{
    float qx = px - tx, qy = py - ty, qz = pz - tz;
    float plx  = qx*r00 + qy*r10 + qz*r20;
    float vlx  = wx*r00 + wy*r10 + wz*r20;
    float ndot = fmaf(-qx, wx, fmaf(-qy, wy, -qz*wz));   // -(P-T).V
    float nn2  = fmaf(-qx, qx, fmaf(-qy, qy, -qz*qz));   // -|P-T|^2
    float vv = vlx * vlx;
    float A  = fmaf(vv, c, mc);                 // c*vlx^2 - c = -c(1-vlx^2)
    float tB = fmaf(plx, vlx, ndot);            // plx*vlx - dot
    float B  = fmaf(twoc, tB, vlx);
    float tC = fmaf(plx, plx, nn2);             // plx^2 - n2
    float C  = fmaf(c, tC, plx);
    if (A == 0.0f) { A = 1.0f; B = 1.0f; C = 0.0f; }     // degenerate guard
    RayQ o;
    o.D  = fmaf(A * C, -4.0f, B * B);           // D = B^2 - 4AC
    o.s  = B;                                   // s0 = B
    o.i4 = frcp_(4.0f * A);                     // 1/(4A)
    return o;
}

__global__ void __launch_bounds__(BLOCK)
lm_kernel(const float* __restrict__ P, const float* __restrict__ V,
          const float* __restrict__ R, const float* __restrict__ T,
          const float* __restrict__ Cs, const float* __restrict__ loss_in,
          float* __restrict__ out, int n, double invN)
{
    const int g = blockIdx.x * BLOCK + threadIdx.x;   // one 8-ray chunk / thread
    const int base = g * 8;

    float ssum = 0.0f;

    if (base < n) {
        const float r00 = __ldg(R + 0), r10 = __ldg(R + 3), r20 = __ldg(R + 6);
        const float tx = __ldg(T + 0), ty = __ldg(T + 1), tz = __ldg(T + 2);
        const float c    = __ldg(Cs);
        const float mc   = -c;
        const float twoc = 2.0f * c;

        RayQ rq[8];
        if (base + 8 <= n) {
            const float4* P4 = (const float4*)P;
            const float4* V4 = (const float4*)V;
            // stage 1: rays 0..3
            {
                float4 a0 = P4[6*g + 0], a1 = P4[6*g + 1], a2 = P4[6*g + 2];
                float4 b0 = V4[6*g + 0], b1 = V4[6*g + 1], b2 = V4[6*g + 2];
                rq[0] = setup_ray(a0.x,a0.y,a0.z, b0.x,b0.y,b0.z, r00,r10,r20, tx,ty,tz, c,mc,twoc);
                rq[1] = setup_ray(a0.w,a1.x,a1.y, b0.w,b1.x,b1.y, r00,r10,r20, tx,ty,tz, c,mc,twoc);
                rq[2] = setup_ray(a1.z,a1.w,a2.x, b1.z,b1.w,b2.x, r00,r10,r20, tx,ty,tz, c,mc,twoc);
                rq[3] = setup_ray(a2.y,a2.z,a2.w, b2.y,b2.z,b2.w, r00,r10,r20, tx,ty,tz, c,mc,twoc);
            }
            // stage 2: rays 4..7
            {
                float4 a0 = P4[6*g + 3], a1 = P4[6*g + 4], a2 = P4[6*g + 5];
                float4 b0 = V4[6*g + 3], b1 = V4[6*g + 4], b2 = V4[6*g + 5];
                rq[4] = setup_ray(a0.x,a0.y,a0.z, b0.x,b0.y,b0.z, r00,r10,r20, tx,ty,tz, c,mc,twoc);
                rq[5] = setup_ray(a0.w,a1.x,a1.y, b0.w,b1.x,b1.y, r00,r10,r20, tx,ty,tz, c,mc,twoc);
                rq[6] = setup_ray(a1.z,a1.w,a2.x, b1.z,b1.w,b2.x, r00,r10,r20, tx,ty,tz, c,mc,twoc);
                rq[7] = setup_ray(a2.y,a2.z,a2.w, b2.y,b2.z,b2.w, r00,r10,r20, tx,ty,tz, c,mc,twoc);
            }
        } else {
            #pragma unroll
            for (int k = 0; k < 8; ++k) {
                int i = base + k;
                if (i < n) {
                    rq[k] = setup_ray(P[3*i],P[3*i+1],P[3*i+2],
                                      V[3*i],V[3*i+1],V[3*i+2],
                                      r00,r10,r20, tx,ty,tz, c,mc,twoc);
                } else {
                    rq[k].D = 1.0f; rq[k].s = 1.0f; rq[k].i4 = 0.25f; // F ends at 0
                }
            }
        }

        const u64 TWO2 = 0x4000000040000000ULL;  // (2, 2)
        const u64 ONE2 = 0x3F8000003F800000ULL;  // (1, 1)

        u64 D[4], s[4], I4[4];
        #pragma unroll
        for (int p = 0; p < 4; ++p) {
            D[p]  = pk2(rq[2*p].D,  rq[2*p+1].D);
            s[p]  = pk2(rq[2*p].s,  rq[2*p+1].s);
            I4[p] = pk2(rq[2*p].i4, rq[2*p+1].i4);
        }

        // 31 LM iterations in s-space: s' = s - s(s^2-D)/(2s^2+1)
        // Two independent shared-reciprocal groups -> 4 dependency chains.
        #pragma unroll
        for (int it = 0; it < NITER; ++it) {
            u64 q0 = fmul2(s[0], s[0]);
            u64 q1 = fmul2(s[1], s[1]);
            u64 q2 = fmul2(s[2], s[2]);
            u64 q3 = fmul2(s[3], s[3]);
            u64 w0 = fsub2(D[0], q0);
            u64 w1 = fsub2(D[1], q1);
            u64 w2 = fsub2(D[2], q2);
            u64 w3 = fsub2(D[3], q3);
            u64 d0 = ffma2(q0, TWO2, ONE2);
            u64 d1 = ffma2(q1, TWO2, ONE2);
            u64 d2 = ffma2(q2, TWO2, ONE2);
            u64 d3 = ffma2(q3, TWO2, ONE2);
            u64 n0 = fmul2(s[0], w0);
            u64 n1 = fmul2(s[1], w1);
            u64 n2 = fmul2(s[2], w2);
            u64 n3 = fmul2(s[3], w3);
            u64 mA = fmul2(d0, d1);
            u64 mB = fmul2(d2, d3);
            float a0, a1, b0, b1;
            up2(mA, a0, a1);
            up2(mB, b0, b1);
            u64 rpA = pk2(frcp_(a0), frcp_(a1));
            u64 rpB = pk2(frcp_(b0), frcp_(b1));
            u64 r0 = fmul2(rpA, d1);
            u64 r1 = fmul2(rpA, d0);
            u64 r2 = fmul2(rpB, d3);
            u64 r3 = fmul2(rpB, d2);
            s[0] = ffma2(n0, r0, s[0]);
            s[1] = ffma2(n1, r1, s[1]);
            s[2] = ffma2(n2, r2, s[2]);
            s[3] = ffma2(n3, r3, s[3]);
        }

        // F = (s^2 - D)/(4A); accumulate F^2
        u64 ss = 0ULL;
        #pragma unroll
        for (int p = 0; p < 4; ++p) {
            u64 q = fmul2(s[p], s[p]);
            u64 w = fsub2(D[p], q);
            u64 F = fmul2(w, I4[p]);
            ss = ffma2(F, F, ss);
        }
        float sa, sb; up2(ss, sa, sb);
        ssum = sa + sb;
    }

    // Block tree reduction (float)
    #pragma unroll
    for (int o = 16; o > 0; o >>= 1)
        ssum += __shfl_xor_sync(0xffffffffu, ssum, o);
    __shared__ float wsum[BLOCK / 32];
    if ((threadIdx.x & 31) == 0) wsum[threadIdx.x >> 5] = ssum;
    __syncthreads();

    // Global double accumulation + last-block finalize (self-resetting for
    // identical behavior on every graph replay).
    if (threadIdx.x == 0) {
        float bsum = 0.0f;
        #pragma unroll
        for (int w = 0; w < BLOCK / 32; ++w) bsum += wsum[w];
        atomicAdd(&g_sum, (double)bsum);
        __threadfence();
        unsigned old = atomicAdd(&g_count, 1u);
        if (old == gridDim.x - 1) {
            __threadfence();
            double tot = g_sum;
            out[0] = (float)((double)loss_in[0] + tot * invN);
            g_sum = 0.0;
            __threadfence();
            g_count = 0;
        }
    }
}

extern "C" void kernel_launch(void* const* d_in, const int* in_sizes, int n_in,
                              void* d_out, int out_size)
{
    const float* P       = (const float*)d_in[0];
    const float* V       = (const float*)d_in[1];
    const float* R       = (const float*)d_in[2];
    const float* T       = (const float*)d_in[3];
    const float* c       = (const float*)d_in[4];
    const float* loss_in = (const float*)d_in[5];

    const int n = in_sizes[0] / 3;                 // number of rays
    int nthreads = (n + 7) / 8;                    // 8 rays per thread
    int nblocks  = (nthreads + BLOCK - 1) / BLOCK; // 2048 for N=4.19M

    lm_kernel<<<nblocks, BLOCK>>>(P, V, R, T, c, loss_in,
                                  (float*)d_out, n, 1.0 / (double)n);
}

// round 7
// speedup vs baseline: 1.2465x; 1.1522x over previous
#include <cuda_runtime.h>

typedef unsigned long long u64;

#define NITER 31
#define BLOCK 256

__device__ double   g_sum   = 0.0;
__device__ unsigned g_count = 0;

__device__ __forceinline__ u64 pk2(float a, float b) {
    u64 r; asm("mov.b64 %0, {%1, %2};" : "=l"(r) : "f"(a), "f"(b)); return r;
}
__device__ __forceinline__ void up2(u64 v, float &a, float &b) {
    asm("mov.b64 {%0, %1}, %2;" : "=f"(a), "=f"(b) : "l"(v));
}
__device__ __forceinline__ u64 ffma2(u64 a, u64 b, u64 c) {
    u64 d; asm("fma.rn.f32x2 %0, %1, %2, %3;" : "=l"(d) : "l"(a), "l"(b), "l"(c)); return d;
}
__device__ __forceinline__ u64 fmul2(u64 a, u64 b) {
    u64 d; asm("mul.rn.f32x2 %0, %1, %2;" : "=l"(d) : "l"(a), "l"(b)); return d;
}
__device__ __forceinline__ u64 fsub2(u64 a, u64 b) {
    u64 d; asm("sub.rn.f32x2 %0, %1, %2;" : "=l"(d) : "l"(a), "l"(b)); return d;
}
__device__ __forceinline__ u64 fadd2(u64 a, u64 b) {
    u64 d; asm("add.rn.f32x2 %0, %1, %2;" : "=l"(d) : "l"(a), "l"(b)); return d;
}
__device__ __forceinline__ float frcp_(float x) {
    float r; asm("rcp.approx.f32 %0, %1;" : "=f"(r) : "f"(x)); return r;
}
// Per-lane k = 2^(127 - exp(q)) so that q*k lands in [1,2). Exact power of two:
// integer ops directly on the two 32-bit halves (alu pipe, no MUFU, no fp rounding).
__device__ __forceinline__ u64 exp_scale(u64 q) {
    u64 k;
    asm("{\n\t"
        ".reg .b32 lo, hi, a, b;\n\t"
        "mov.b64 {lo, hi}, %1;\n\t"
        "and.b32 a, lo, 0x7F800000;\n\t"
        "and.b32 b, hi, 0x7F800000;\n\t"
        "sub.u32 a, 0x7F000000, a;\n\t"
        "sub.u32 b, 0x7F000000, b;\n\t"
        "mov.b64 %0, {a, b};\n\t"
        "}" : "=l"(k) : "l"(q));
    return k;
}

// Per-ray quadratic setup using |V_local| = 1 and rotation invariance:
//   A = -c (1 - vlx^2),  B = vlx + 2c (plx*vlx - (P-T).V),
//   C = plx + c (plx^2 - |P-T|^2).   Only column 0 of R is needed.
struct RayQ { float E, s, i4; };   // E = D+1, s0 = B, i4 = 1/(4A)

__device__ __forceinline__ RayQ setup_ray(
    float px, float py, float pz, float wx, float wy, float wz,
    float r00, float r10, float r20, float tx, float ty, float tz,
    float c, float mc, float twoc)
{
    float qx = px - tx, qy = py - ty, qz = pz - tz;
    float plx  = qx*r00 + qy*r10 + qz*r20;
    float vlx  = wx*r00 + wy*r10 + wz*r20;
    float ndot = fmaf(-qx, wx, fmaf(-qy, wy, -qz*wz));   // -(P-T).V
    float nn2  = fmaf(-qx, qx, fmaf(-qy, qy, -qz*qz));   // -|P-T|^2
    float A  = fmaf(vlx*vlx, c, mc);            // -c(1-vlx^2)
    float B  = fmaf(twoc, fmaf(plx, vlx, ndot), vlx);
    float C  = fmaf(c, fmaf(plx, plx, nn2), plx);
    if (A == 0.0f) { A = 1.0f; B = 1.0f; C = 0.0f; }     // degenerate guard
    RayQ o;
    float D = fmaf(A * C, -4.0f, B * B);        // D = B^2 - 4AC
    o.E  = D + 1.0f;
    o.s  = B;
    o.i4 = frcp_(4.0f * A);
    return o;
}

__global__ void __launch_bounds__(BLOCK)
lm_kernel(const float* __restrict__ P, const float* __restrict__ V,
          const float* __restrict__ R, const float* __restrict__ T,
          const float* __restrict__ Cs, const float* __restrict__ loss_in,
          float* __restrict__ out, int n, double invN)
{
    const int g = blockIdx.x * BLOCK + threadIdx.x;   // 8 rays / thread
    const int base = g * 8;

    float ssum = 0.0f;

    if (base < n) {
        const float r00 = __ldg(R + 0), r10 = __ldg(R + 3), r20 = __ldg(R + 6);
        const float tx = __ldg(T + 0), ty = __ldg(T + 1), tz = __ldg(T + 2);
        const float c    = __ldg(Cs);
        const float mc   = -c;
        const float twoc = 2.0f * c;

        RayQ rq[8];
        if (base + 8 <= n) {
            const float4* P4 = (const float4*)P;
            const float4* V4 = (const float4*)V;
            {
                float4 a0 = P4[6*g + 0], a1 = P4[6*g + 1], a2 = P4[6*g + 2];
                float4 b0 = V4[6*g + 0], b1 = V4[6*g + 1], b2 = V4[6*g + 2];
                rq[0] = setup_ray(a0.x,a0.y,a0.z, b0.x,b0.y,b0.z, r00,r10,r20, tx,ty,tz, c,mc,twoc);
                rq[1] = setup_ray(a0.w,a1.x,a1.y, b0.w,b1.x,b1.y, r00,r10,r20, tx,ty,tz, c,mc,twoc);
                rq[2] = setup_ray(a1.z,a1.w,a2.x, b1.z,b1.w,b2.x, r00,r10,r20, tx,ty,tz, c,mc,twoc);
                rq[3] = setup_ray(a2.y,a2.z,a2.w, b2.y,b2.z,b2.w, r00,r10,r20, tx,ty,tz, c,mc,twoc);
            }
            {
                float4 a0 = P4[6*g + 3], a1 = P4[6*g + 4], a2 = P4[6*g + 5];
                float4 b0 = V4[6*g + 3], b1 = V4[6*g + 4], b2 = V4[6*g + 5];
                rq[4] = setup_ray(a0.x,a0.y,a0.z, b0.x,b0.y,b0.z, r00,r10,r20, tx,ty,tz, c,mc,twoc);
                rq[5] = setup_ray(a0.w,a1.x,a1.y, b0.w,b1.x,b1.y, r00,r10,r20, tx,ty,tz, c,mc,twoc);
                rq[6] = setup_ray(a1.z,a1.w,a2.x, b1.z,b1.w,b2.x, r00,r10,r20, tx,ty,tz, c,mc,twoc);
                rq[7] = setup_ray(a2.y,a2.z,a2.w, b2.y,b2.z,b2.w, r00,r10,r20, tx,ty,tz, c,mc,twoc);
            }
        } else {
            #pragma unroll
            for (int k = 0; k < 8; ++k) {
                int i = base + k;
                if (i < n) {
                    rq[k] = setup_ray(P[3*i],P[3*i+1],P[3*i+2],
                                      V[3*i],V[3*i+1],V[3*i+2],
                                      r00,r10,r20, tx,ty,tz, c,mc,twoc);
                } else {
                    rq[k].E = 2.0f; rq[k].s = 1.0f; rq[k].i4 = 0.25f; // F ends 0
                }
            }
        }

        const u64 TWO2 = 0x4000000040000000ULL;  // (2, 2)
        const u64 ONE2 = 0x3F8000003F800000ULL;  // (1, 1)

        u64 E[4], p[4], q[4], I4[4];
        #pragma unroll
        for (int k = 0; k < 4; ++k) {
            E[k]  = pk2(rq[2*k].E,  rq[2*k+1].E);
            p[k]  = pk2(rq[2*k].s,  rq[2*k+1].s);   // s = p/q, q0 = 1
            q[k]  = ONE2;
            I4[k] = pk2(rq[2*k].i4, rq[2*k+1].i4);
        }

        // Projective LM: s' = s(s^2+E)/(2s^2+1)  =>
        //   p' = p (p^2 + E q^2),  q' = q (2 p^2 + q^2)
        // Division-free; renormalize by an exact power of two every 2nd iter.
        #pragma unroll
        for (int it = 0; it < NITER; ++it) {
            #pragma unroll
            for (int k = 0; k < 4; ++k) {
                u64 pp = fmul2(p[k], p[k]);
                u64 qq = fmul2(q[k], q[k]);
                u64 u  = ffma2(E[k], qq, pp);    // p^2 + E q^2
                u64 v  = ffma2(pp, TWO2, qq);    // 2 p^2 + q^2
                p[k] = fmul2(p[k], u);
                q[k] = fmul2(q[k], v);
            }
            if (it & 1) {
                #pragma unroll
                for (int k = 0; k < 4; ++k) {
                    u64 sc = exp_scale(q[k]);    // exact 2^-e, q*sc in [1,2)
                    p[k] = fmul2(p[k], sc);
                    q[k] = fmul2(q[k], sc);
                }
            }
        }

        // Epilogue: s = p/q (rcp only here), F = (s^2 - D) i4 = (s^2 - E + 1) i4
        u64 ss = 0ULL;
        #pragma unroll
        for (int k = 0; k < 4; ++k) {
            float qa, qb; up2(q[k], qa, qb);
            u64 rq2 = pk2(frcp_(qa), frcp_(qb));
            u64 s  = fmul2(p[k], rq2);
            u64 qs = fmul2(s, s);
            u64 t  = fsub2(qs, E[k]);            // s^2 - D - 1
            u64 w  = fadd2(t, ONE2);             // s^2 - D
            u64 F  = fmul2(w, I4[k]);
            ss = ffma2(F, F, ss);
        }
        float sa, sb; up2(ss, sa, sb);
        ssum = sa + sb;
    }

    // Block tree reduction (float)
    #pragma unroll
    for (int o = 16; o > 0; o >>= 1)
        ssum += __shfl_xor_sync(0xffffffffu, ssum, o);
    __shared__ float wsum[BLOCK / 32];
    if ((threadIdx.x & 31) == 0) wsum[threadIdx.x >> 5] = ssum;
    __syncthreads();

    // Global double accumulation + last-block finalize (self-resetting for
    // identical behavior on every graph replay).
    if (threadIdx.x == 0) {
        float bsum = 0.0f;
        #pragma unroll
        for (int w = 0; w < BLOCK / 32; ++w) bsum += wsum[w];
        atomicAdd(&g_sum, (double)bsum);
        __threadfence();
        unsigned old = atomicAdd(&g_count, 1u);
        if (old == gridDim.x - 1) {
            __threadfence();
            double tot = g_sum;
            out[0] = (float)((double)loss_in[0] + tot * invN);
            g_sum = 0.0;
            __threadfence();
            g_count = 0;
        }
    }
}

extern "C" void kernel_launch(void* const* d_in, const int* in_sizes, int n_in,
                              void* d_out, int out_size)
{
    const float* P       = (const float*)d_in[0];
    const float* V       = (const float*)d_in[1];
    const float* R       = (const float*)d_in[2];
    const float* T       = (const float*)d_in[3];
    const float* c       = (const float*)d_in[4];
    const float* loss_in = (const float*)d_in[5];

    const int n = in_sizes[0] / 3;                 // number of rays
    int nthreads = (n + 7) / 8;                    // 8 rays per thread
    int nblocks  = (nthreads + BLOCK - 1) / BLOCK; // 2048 for N=4.19M

    lm_kernel<<<nblocks, BLOCK>>>(P, V, R, T, c, loss_in,
                                  (float*)d_out, n, 1.0 / (double)n);
}